// round 1
// baseline (speedup 1.0000x reference)
#include <cuda_runtime.h>
#include <math.h>
#include <stdint.h>

#define T_TOK 16384
#define H_DIM 2048
#define E_NUM 16
#define I_DIM 1408
#define TWOI  2816
#define S_SLOTS (T_TOK*2)

// ---------------- scratch (device globals: no allocations allowed) ----------
__device__ int   g_counts[E_NUM];
__device__ int   g_fill[E_NUM];
__device__ int   g_offs[E_NUM+1];
__device__ int   g_ids[S_SLOTS];
__device__ float g_topw[S_SLOTS];
__device__ int   g_perm[S_SLOTS];          // slot -> token
__device__ int   g_slot[S_SLOTS];          // (token,k) -> slot
__device__ float g_gbuf[(size_t)S_SLOTS * TWOI];   // 369 MB: g = x @ w13^T
__device__ float g_actb[(size_t)S_SLOTS * I_DIM];  // 184 MB: silu(g1)*g2
__device__ float g_ybuf[(size_t)S_SLOTS * H_DIM];  // 256 MB: act @ w2^T

// ---------------- routing ---------------------------------------------------
__global__ void init_kernel() {
    int i = threadIdx.x;
    if (i < E_NUM) { g_counts[i] = 0; g_fill[i] = 0; }
}

__global__ void route_kernel(const float* __restrict__ logits) {
    int t = blockIdx.x * blockDim.x + threadIdx.x;
    if (t >= T_TOK) return;
    float l[E_NUM];
#pragma unroll
    for (int e = 0; e < E_NUM; e++) l[e] = logits[t * E_NUM + e];
    int e0 = 0; float m0 = l[0];
#pragma unroll
    for (int e = 1; e < E_NUM; e++) if (l[e] > m0) { m0 = l[e]; e0 = e; }
    int e1 = -1; float m1 = -1e30f;
#pragma unroll
    for (int e = 0; e < E_NUM; e++) if (e != e0 && l[e] > m1) { m1 = l[e]; e1 = e; }
    // renormalized top-2 softmax weights: w0 = p0/(p0+p1) = sigmoid(l0-l1)
    float w0 = 1.f / (1.f + expf(m1 - m0));
    float w1 = 1.f - w0;
    g_ids[2*t] = e0;  g_ids[2*t+1] = e1;
    g_topw[2*t] = w0; g_topw[2*t+1] = w1;
    atomicAdd(&g_counts[e0], 1);
    atomicAdd(&g_counts[e1], 1);
}

__global__ void scan_kernel() {
    if (threadIdx.x == 0) {
        int acc = 0; g_offs[0] = 0;
        for (int e = 0; e < E_NUM; e++) { acc += g_counts[e]; g_offs[e+1] = acc; }
    }
}

__global__ void perm_kernel() {
    int t = blockIdx.x * blockDim.x + threadIdx.x;
    if (t >= T_TOK) return;
#pragma unroll
    for (int s = 0; s < 2; s++) {
        int e = g_ids[2*t+s];
        int pos = g_offs[e] + atomicAdd(&g_fill[e], 1);
        g_perm[pos] = t;
        g_slot[2*t+s] = pos;
    }
}

// ---------------- tf32 mma helpers ------------------------------------------
__device__ __forceinline__ uint32_t f2tf(float x) {
    uint32_t r; asm("cvt.rna.tf32.f32 %0, %1;" : "=r"(r) : "f"(x)); return r;
}
__device__ __forceinline__ void mma8(float* c, const uint32_t* a, const uint32_t* b) {
    asm volatile(
        "mma.sync.aligned.m16n8k8.row.col.f32.tf32.tf32.f32 "
        "{%0,%1,%2,%3},{%4,%5,%6,%7},{%8,%9},{%0,%1,%2,%3};"
        : "+f"(c[0]), "+f"(c[1]), "+f"(c[2]), "+f"(c[3])
        : "r"(a[0]), "r"(a[1]), "r"(a[2]), "r"(a[3]), "r"(b[0]), "r"(b[1]));
}

// ---------------- grouped GEMM: C[slot, n] = A[slot,:] . B_e[n,:] ------------
// G1=true : A = hidden[perm[slot]] (K=H),   B = w13[e] [2I,H],  C = g_gbuf [*,2I]
// G1=false: A = g_actb[slot]       (K=I),   B = w2[e]  [H,I],   C = g_ybuf [*,H]
#define LDG_TILE(kt) {                                                   \
    const float* ap_ = arow + (kt)*16 + khalf;                           \
    const float* bp_ = brow + (kt)*16 + khalf;                           \
    ra0 = *(const float4*)(ap_);  ra1 = *(const float4*)(ap_ + 4);       \
    rb0 = *(const float4*)(bp_);  rb1 = *(const float4*)(bp_ + 4); }

#define STS_TILE(buf) {                                                  \
    float* as_ = &As[buf][khalf][lrow];                                  \
    float* bs_ = &Bs[buf][khalf][lrow];                                  \
    as_[0*136]=ra0.x; as_[1*136]=ra0.y; as_[2*136]=ra0.z; as_[3*136]=ra0.w; \
    as_[4*136]=ra1.x; as_[5*136]=ra1.y; as_[6*136]=ra1.z; as_[7*136]=ra1.w; \
    bs_[0*136]=rb0.x; bs_[1*136]=rb0.y; bs_[2*136]=rb0.z; bs_[3*136]=rb0.w; \
    bs_[4*136]=rb1.x; bs_[5*136]=rb1.y; bs_[6*136]=rb1.z; bs_[7*136]=rb1.w; }

template<int KDIM, int NB, int CLD, bool G1>
__global__ __launch_bounds__(256, 2) void moe_gemm(
    const float* __restrict__ Aext, const float* __restrict__ Bext)
{
    int e     = blockIdx.z;
    int off   = g_offs[e];
    int cnt   = g_offs[e+1] - off;
    int mbase = blockIdx.y * 128;
    if (mbase >= cnt) return;
    int rowsValid = cnt - mbase;                 // rows in this tile (<=128)
    int slot0 = off + mbase;
    int nbase = blockIdx.x * 128;

    __shared__ float As[2][16][136];             // [k][m], pad 8 -> conflict-free frags
    __shared__ float Bs[2][16][136];             // [k][n]

    int tid   = threadIdx.x;
    int lrow  = tid >> 1;                        // 0..127
    int khalf = (tid & 1) * 8;                   // 0 or 8

    int slot = slot0 + lrow;
    if (slot > S_SLOTS - 1) slot = S_SLOTS - 1;  // clamp; stores are masked anyway
    const float* arow = G1 ? (Aext + (size_t)g_perm[slot] * KDIM)
                           : (&g_actb[(size_t)slot * KDIM]);
    const float* brow = Bext + ((size_t)e * NB + nbase + lrow) * KDIM;
    float* Cbase = G1 ? g_gbuf : g_ybuf;

    int lane = tid & 31;
    int warp = tid >> 5;
    int wm = (warp & 1) * 64;                    // 2x4 warp grid -> 64x32 warp tiles
    int wn = (warp >> 1) * 32;
    int tr = lane >> 2;                          // groupID
    int tc = lane & 3;                           // threadID-in-group

    float acc[4][4][4];
#pragma unroll
    for (int a = 0; a < 4; a++)
#pragma unroll
        for (int b = 0; b < 4; b++)
#pragma unroll
            for (int c = 0; c < 4; c++) acc[a][b][c] = 0.f;

    float4 ra0, ra1, rb0, rb1;
    constexpr int NK = KDIM / 16;

    LDG_TILE(0);
    STS_TILE(0);
    __syncthreads();

    for (int kt = 0; kt < NK; kt++) {
        int cur = kt & 1;
        if (kt + 1 < NK) LDG_TILE(kt + 1);       // global prefetch overlaps compute
#pragma unroll
        for (int ks = 0; ks < 2; ks++) {
            int kb = ks * 8;
            uint32_t af[4][4], bf[4][2];
#pragma unroll
            for (int mi = 0; mi < 4; mi++) {
                int r = wm + mi * 16 + tr;
                af[mi][0] = f2tf(As[cur][kb + tc    ][r    ]);
                af[mi][1] = f2tf(As[cur][kb + tc    ][r + 8]);
                af[mi][2] = f2tf(As[cur][kb + tc + 4][r    ]);
                af[mi][3] = f2tf(As[cur][kb + tc + 4][r + 8]);
            }
#pragma unroll
            for (int ni = 0; ni < 4; ni++) {
                int c = wn + ni * 8 + tr;
                bf[ni][0] = f2tf(Bs[cur][kb + tc    ][c]);
                bf[ni][1] = f2tf(Bs[cur][kb + tc + 4][c]);
            }
#pragma unroll
            for (int mi = 0; mi < 4; mi++)
#pragma unroll
                for (int ni = 0; ni < 4; ni++)
                    mma8(acc[mi][ni], af[mi], bf[ni]);
        }
        if (kt + 1 < NK) {
            STS_TILE((kt + 1) & 1);              // safe: other buffer, prev sync drained
            __syncthreads();
        }
    }

#pragma unroll
    for (int mi = 0; mi < 4; mi++) {
        int r0 = wm + mi * 16 + tr;
        int r1 = r0 + 8;
#pragma unroll
        for (int ni = 0; ni < 4; ni++) {
            int c = nbase + wn + ni * 8 + tc * 2;
            if (r0 < rowsValid) {
                float2 v; v.x = acc[mi][ni][0]; v.y = acc[mi][ni][1];
                *(float2*)&Cbase[(size_t)(slot0 + r0) * CLD + c] = v;
            }
            if (r1 < rowsValid) {
                float2 v; v.x = acc[mi][ni][2]; v.y = acc[mi][ni][3];
                *(float2*)&Cbase[(size_t)(slot0 + r1) * CLD + c] = v;
            }
        }
    }
}
#undef LDG_TILE
#undef STS_TILE

// ---------------- silu-and-mul ----------------------------------------------
__global__ void silu_kernel() {
    const int per_row = I_DIM / 4;               // 352 float4 per row
    int idx = blockIdx.x * blockDim.x + threadIdx.x;
    if (idx >= S_SLOTS * per_row) return;
    int row = idx / per_row;
    int c4  = idx % per_row;
    const float4* gp = (const float4*)&g_gbuf[(size_t)row * TWOI];
    float4 g = gp[c4];
    float4 u = gp[c4 + per_row];                 // +I_DIM elements
    float4 o;
    o.x = g.x / (1.f + expf(-g.x)) * u.x;
    o.y = g.y / (1.f + expf(-g.y)) * u.y;
    o.z = g.z / (1.f + expf(-g.z)) * u.z;
    o.w = g.w / (1.f + expf(-g.w)) * u.w;
    ((float4*)&g_actb[(size_t)row * I_DIM])[c4] = o;
}

// ---------------- weighted combine (exactly 2 slots per token) ---------------
__global__ void combine_kernel(float* __restrict__ out) {
    const int per_row = H_DIM / 4;               // 512 float4 per row
    int idx = blockIdx.x * blockDim.x + threadIdx.x;
    if (idx >= T_TOK * per_row) return;
    int t = idx / per_row;
    int h = idx % per_row;
    int p0 = g_slot[2*t], p1 = g_slot[2*t+1];
    float w0 = g_topw[2*t], w1 = g_topw[2*t+1];
    float4 y0 = ((const float4*)&g_ybuf[(size_t)p0 * H_DIM])[h];
    float4 y1 = ((const float4*)&g_ybuf[(size_t)p1 * H_DIM])[h];
    float4 o;
    o.x = w0 * y0.x + w1 * y1.x;
    o.y = w0 * y0.y + w1 * y1.y;
    o.z = w0 * y0.z + w1 * y1.z;
    o.w = w0 * y0.w + w1 * y1.w;
    ((float4*)out)[idx] = o;
}

// ---------------- launch -----------------------------------------------------
extern "C" void kernel_launch(void* const* d_in, const int* in_sizes, int n_in,
                              void* d_out, int out_size) {
    (void)in_sizes; (void)n_in; (void)out_size;
    const float* hidden = (const float*)d_in[0];
    const float* logits = (const float*)d_in[1];
    const float* w13    = (const float*)d_in[2];
    const float* w2     = (const float*)d_in[3];
    float* out = (float*)d_out;

    init_kernel<<<1, 32>>>();
    route_kernel<<<T_TOK / 256, 256>>>(logits);
    scan_kernel<<<1, 1>>>();
    perm_kernel<<<T_TOK / 256, 256>>>();

    // GEMM1: [M_e,2816] = gathered_hidden @ w13_e^T  (K=2048)
    moe_gemm<H_DIM, TWOI, TWOI, true>
        <<<dim3(TWOI / 128, T_TOK / 128, E_NUM), 256>>>(hidden, w13);

    int ns = S_SLOTS * (I_DIM / 4);
    silu_kernel<<<(ns + 255) / 256, 256>>>();

    // GEMM2: [M_e,2048] = act @ w2_e^T  (K=1408)
    moe_gemm<I_DIM, H_DIM, H_DIM, false>
        <<<dim3(H_DIM / 128, T_TOK / 128, E_NUM), 256>>>(nullptr, w2);

    int nc = T_TOK * (H_DIM / 4);
    combine_kernel<<<(nc + 255) / 256, 256>>>(out);
}